// round 13
// baseline (speedup 1.0000x reference)
#include <cuda_runtime.h>
#include <cuda_fp16.h>
#include <stdint.h>

#define DIM 128
#define GT 128        // gate tile rows
#define AT 256        // agg tile rows
#define NT 256
#define SH 136        // half stride: word-stride 68 = 4 mod 32 -> conflict-free frags
#define SEG_SENT 0x7FFFFFFF
#define MAXN 1100000
#define MAXSEG 8192
#define AGRID 152

// ---------------- scratch ----------------
__device__ float g_gate[MAXN];        // g, then e
__device__ float g_segmax[MAXSEG];
__device__ float g_segsum[MAXSEG];
__device__ int   g_idx_is64;

// ---------------- helpers ----------------
__device__ __forceinline__ float silu_f(float a) {
    return __fdividef(a, 1.0f + __expf(-a));
}
__device__ __forceinline__ uint32_t pack_half2(float lo, float hi) {
    uint32_t u; asm("cvt.rn.f16x2.f32 %0, %1, %2;" : "=r"(u) : "f"(hi), "f"(lo)); return u;
}
__device__ __forceinline__ void atomicMaxF(float* addr, float v) {
    int old = __float_as_int(*addr);
    while (__int_as_float(old) < v) {
        int prev = atomicCAS((int*)addr, old, __float_as_int(v));
        if (prev == old) break;
        old = prev;
    }
}
__device__ __forceinline__ int load_index(const void* p, int i, bool is64) {
    return is64 ? (int)((const long long*)p)[i] : ((const int*)p)[i];
}
__device__ __forceinline__ void mma_f16(float c[4], const uint32_t a[4], uint32_t b0, uint32_t b1) {
    asm volatile(
        "mma.sync.aligned.m16n8k16.row.col.f32.f16.f16.f32 "
        "{%0,%1,%2,%3}, {%4,%5,%6,%7}, {%8,%9}, {%0,%1,%2,%3};"
        : "+f"(c[0]), "+f"(c[1]), "+f"(c[2]), "+f"(c[3])
        : "r"(a[0]), "r"(a[1]), "r"(a[2]), "r"(a[3]), "r"(b0), "r"(b1));
}

// W[k][n] fp32 row-major -> smem transposed half [n*SH + k], MLP-batched
__device__ __forceinline__ void load_w16(__half* swh, const float* __restrict__ W, int tid) {
    #pragma unroll
    for (int b = 0; b < 2; ++b) {
        float4 v[8];
        #pragma unroll
        for (int i = 0; i < 8; ++i) v[i] = ((const float4*)W)[tid + (b * 8 + i) * NT];
        #pragma unroll
        for (int i = 0; i < 8; ++i) {
            int q = tid + (b * 8 + i) * NT;
            int k = q >> 5, nv = (q & 31) * 4;
            swh[(nv + 0) * SH + k] = __float2half_rn(v[i].x);
            swh[(nv + 1) * SH + k] = __float2half_rn(v[i].y);
            swh[(nv + 2) * SH + k] = __float2half_rn(v[i].z);
            swh[(nv + 3) * SH + k] = __float2half_rn(v[i].w);
        }
    }
}

// fp32 ROWS-row tile -> half smem [row*SH + col], MLP-batched (8 LDG.128 in flight)
template<int ROWS>
__device__ __forceinline__ void load_x16(__half* sx, const float* __restrict__ x,
                                         int base, int N, int tid) {
    #pragma unroll
    for (int b = 0; b < ROWS / 64; ++b) {
        float4 v[8];
        #pragma unroll
        for (int i = 0; i < 8; ++i) {
            int q = tid + (b * 8 + i) * NT;
            int node = base + (q >> 5);
            v[i] = (node < N) ? ((const float4*)x)[(size_t)node * 32 + (q & 31)]
                              : make_float4(0.f, 0.f, 0.f, 0.f);
        }
        #pragma unroll
        for (int i = 0; i < 8; ++i) {
            int q = tid + (b * 8 + i) * NT;
            int n = q >> 5, kv = q & 31;
            uint2 pk;
            pk.x = pack_half2(v[i].x, v[i].y);
            pk.y = pack_half2(v[i].z, v[i].w);
            *(uint2*)&sx[n * SH + kv * 4] = pk;
        }
    }
}

// 32x64 warp-tile GEMM (gate): K=128 in 8 k16 steps.
__device__ __forceinline__ void warp_gemm16(const __half* __restrict__ sx,
                                            const __half* __restrict__ sW,
                                            float acc[2][8][4], int m0, int n0, int lane) {
    const int ar = lane >> 2, ac = lane & 3;
    #pragma unroll
    for (int ks = 0; ks < 8; ++ks) {
        const int k0 = ks * 16;
        uint32_t a[2][4];
        #pragma unroll
        for (int mi = 0; mi < 2; ++mi) {
            const __half* xb = sx + (m0 + mi * 16 + ar) * SH + k0 + 2 * ac;
            a[mi][0] = *(const uint32_t*)(xb);
            a[mi][1] = *(const uint32_t*)(xb + 8 * SH);
            a[mi][2] = *(const uint32_t*)(xb + 8);
            a[mi][3] = *(const uint32_t*)(xb + 8 * SH + 8);
        }
        const __half* wb = sW + (n0 + ar) * SH + k0 + 2 * ac;
        #pragma unroll
        for (int j = 0; j < 8; ++j) {
            uint32_t b0 = *(const uint32_t*)(wb + j * 8 * SH);
            uint32_t b1 = *(const uint32_t*)(wb + j * 8 * SH + 8);
            mma_f16(acc[0][j], a[0], b0, b1);
            mma_f16(acc[1][j], a[1], b0, b1);
        }
    }
}

// 32x128 full-n warp-tile GEMM (agg GEMM1): A from smem
__device__ __forceinline__ void warp_gemm_fn(const __half* __restrict__ sx,
                                             const __half* __restrict__ sW,
                                             float acc[2][16][4], int m0, int lane) {
    const int ar = lane >> 2, ac = lane & 3;
    #pragma unroll
    for (int ks = 0; ks < 8; ++ks) {
        const int k0 = ks * 16;
        uint32_t a[2][4];
        #pragma unroll
        for (int mi = 0; mi < 2; ++mi) {
            const __half* xb = sx + (m0 + mi * 16 + ar) * SH + k0 + 2 * ac;
            a[mi][0] = *(const uint32_t*)(xb);
            a[mi][1] = *(const uint32_t*)(xb + 8 * SH);
            a[mi][2] = *(const uint32_t*)(xb + 8);
            a[mi][3] = *(const uint32_t*)(xb + 8 * SH + 8);
        }
        const __half* wb = sW + ar * SH + k0 + 2 * ac;
        #pragma unroll
        for (int j = 0; j < 16; ++j) {
            uint32_t b0 = *(const uint32_t*)(wb + j * 8 * SH);
            uint32_t b1 = *(const uint32_t*)(wb + j * 8 * SH + 8);
            mma_f16(acc[0][j], a[0], b0, b1);
            mma_f16(acc[1][j], a[1], b0, b1);
        }
    }
}

// 32x128 full-n warp-tile GEMM (agg GEMM2): A from register t-fragments.
// D-frag of GEMM1 (j-block n-cols) == A-frag k-cols for GEMM2; k-step ks uses j=2ks, 2ks+1.
__device__ __forceinline__ void warp_gemm_t(const uint32_t t[2][16][2],
                                            const __half* __restrict__ sW,
                                            float acc[2][16][4], int lane) {
    const int ar = lane >> 2, ac = lane & 3;
    #pragma unroll
    for (int ks = 0; ks < 8; ++ks) {
        const int k0 = ks * 16;
        uint32_t a[2][4];
        #pragma unroll
        for (int mi = 0; mi < 2; ++mi) {
            a[mi][0] = t[mi][2 * ks][0];
            a[mi][1] = t[mi][2 * ks][1];
            a[mi][2] = t[mi][2 * ks + 1][0];
            a[mi][3] = t[mi][2 * ks + 1][1];
        }
        const __half* wb = sW + ar * SH + k0 + 2 * ac;
        #pragma unroll
        for (int j = 0; j < 16; ++j) {
            uint32_t b0 = *(const uint32_t*)(wb + j * 8 * SH);
            uint32_t b1 = *(const uint32_t*)(wb + j * 8 * SH + 8);
            mma_f16(acc[0][j], a[0], b0, b1);
            mma_f16(acc[1][j], a[1], b0, b1);
        }
    }
}

// ---------------- detect + segment init ----------------
__global__ void di_kernel(const int* v, int n, int S) {
    if (blockIdx.x == 0) {
        int p = n - 1 - (int)threadIdx.x;
        int nz = 0;
        if (p >= 0 && (p & 1) && v[p] != 0) nz = 1;
        int any = __syncthreads_or(nz);
        if (threadIdx.x == 0) g_idx_is64 = any ? 0 : 1;
    }
    int i = blockIdx.x * blockDim.x + threadIdx.x;
    int stride = gridDim.x * blockDim.x;
    for (int p = i; p < S; p += stride) { g_segmax[p] = -3.0e38f; g_segsum[p] = 0.0f; }
}

// softmax + zero out (out must be zeroed before agg)
__global__ void softmax_kernel(const void* __restrict__ idxp, int N,
                               float* __restrict__ out, int out_n) {
    const bool is64 = (g_idx_is64 != 0);
    int stride = gridDim.x * blockDim.x;
    int i0 = blockIdx.x * blockDim.x + threadIdx.x;
    for (int p = i0; p < out_n; p += stride) out[p] = 0.0f;
    for (int i = i0; i < N; i += stride) {
        int id = load_index(idxp, i, is64);
        float e = __expf(g_gate[i] - g_segmax[id]);
        g_gate[i] = e;
        bool done = false;
        unsigned m = __activemask();
        if (m == 0xffffffffu) {
            int id0 = __shfl_sync(m, id, 0);
            if (__all_sync(m, id == id0)) {
                float s = e;
                #pragma unroll
                for (int off = 16; off; off >>= 1) s += __shfl_xor_sync(m, s, off);
                if ((threadIdx.x & 31) == 0) atomicAdd(&g_segsum[id0], s);
                done = true;
            }
        }
        if (!done) atomicAdd(&g_segsum[id], e);
    }
}

// ---------------- pass 1: gate GEMM (fp16) + segment max (unchanged from R12) ----------------
// bytes: sW@0(34816) sx@34816(34816) b1@69632(512) w2@70144(512) sg@70656(1024) idx@71680(512)
#define G_SMEM_BYTES 72192

__global__ __launch_bounds__(NT, 2)
void gate_kernel(const float* __restrict__ x, const void* __restrict__ idxp,
                 const float* __restrict__ Wg1, const float* __restrict__ bg1,
                 const float* __restrict__ Wg2, const float* __restrict__ bg2, int N) {
    extern __shared__ char smb[];
    __half* sW  = (__half*)smb;
    __half* sx  = (__half*)(smb + 34816);
    float* sb1  = (float*)(smb + 69632);
    float* sw2  = (float*)(smb + 70144);
    float* sg   = (float*)(smb + 70656);
    int*  sidx  = (int*)(smb + 71680);

    const int tid = threadIdx.x;
    const int w = tid >> 5, lane = tid & 31;
    const int ar = lane >> 2, ac = lane & 3;
    const int mq = w & 3, nh = w >> 2;
    const bool is64 = (g_idx_is64 != 0);

    load_w16(sW, Wg1, tid);
    if (tid < DIM) { sb1[tid] = bg1[tid]; sw2[tid] = Wg2[tid]; }
    const float bg2v = bg2[0];
    __syncthreads();

    const int ntiles = (N + GT - 1) / GT;
    for (int tile = blockIdx.x; tile < ntiles; tile += gridDim.x) {
        const int base = tile * GT;

        load_x16<GT>(sx, x, base, N, tid);
        if (tid < GT) {
            int node = base + tid;
            sidx[tid] = (node < N) ? load_index(idxp, node, is64) : -1;
        }
        __syncthreads();

        float acc[2][8][4];
        #pragma unroll
        for (int mi = 0; mi < 2; ++mi)
            #pragma unroll
            for (int j = 0; j < 8; ++j)
                #pragma unroll
                for (int c = 0; c < 4; ++c) acc[mi][j][c] = 0.0f;
        warp_gemm16(sx, sW, acc, mq * 32, nh * 64, lane);

        #pragma unroll
        for (int mi = 0; mi < 2; ++mi) {
            float p0 = 0.0f, p1 = 0.0f;
            #pragma unroll
            for (int j = 0; j < 8; ++j) {
                int c = nh * 64 + 8 * j + 2 * ac;
                float s0 = sw2[c], s1 = sw2[c + 1];
                float u0 = sb1[c], u1 = sb1[c + 1];
                p0 = fmaf(silu_f(acc[mi][j][0] + u0), s0, p0);
                p0 = fmaf(silu_f(acc[mi][j][1] + u1), s1, p0);
                p1 = fmaf(silu_f(acc[mi][j][2] + u0), s0, p1);
                p1 = fmaf(silu_f(acc[mi][j][3] + u1), s1, p1);
            }
            p0 += __shfl_xor_sync(0xffffffffu, p0, 1);
            p0 += __shfl_xor_sync(0xffffffffu, p0, 2);
            p1 += __shfl_xor_sync(0xffffffffu, p1, 1);
            p1 += __shfl_xor_sync(0xffffffffu, p1, 2);
            if (ac == 0) {
                int r = mq * 32 + mi * 16 + ar;
                sg[nh * 128 + r] = p0;
                sg[nh * 128 + r + 8] = p1;
            }
        }
        __syncthreads();

        if (tid < GT) {
            float g = sg[tid] + sg[128 + tid] + bg2v;
            int node = base + tid;
            if (node < N) g_gate[node] = g;
            int id = sidx[tid];
            float v = (id >= 0) ? g : -3.0e38f;
            #pragma unroll
            for (int off = 1; off < 32; off <<= 1) {
                float ov = __shfl_down_sync(0xffffffffu, v, off);
                int  oid = __shfl_down_sync(0xffffffffu, id, off);
                if (lane + off < 32 && oid == id) v = fmaxf(v, ov);
            }
            int pid = __shfl_up_sync(0xffffffffu, id, 1);
            if (((lane == 0) || (pid != id)) && id >= 0) atomicMaxF(&g_segmax[id], v);
        }
        __syncthreads();
    }
}

// ---------------- pass 3: register-t node MLP, double-buffered x, 1 barrier/tile ----------------
// bytes: sW1@0(34816) sW2@34816 sx0@69632(69632) sx1@139264(69632)
//        b1@208896(512) b2@209408(512) attn@209920(2048) idx@211968(2048)
#define A_SMEM_BYTES 214016

__global__ __launch_bounds__(NT, 1)
void agg_kernel(const float* __restrict__ x, const void* __restrict__ idxp,
                const float* __restrict__ Wn1, const float* __restrict__ bn1,
                const float* __restrict__ Wn2, const float* __restrict__ bn2,
                float* __restrict__ out, int N) {
    extern __shared__ char smb[];
    __half* sW1  = (__half*)smb;
    __half* sW2  = (__half*)(smb + 34816);
    __half* sx0  = (__half*)(smb + 69632);
    __half* sx1  = (__half*)(smb + 139264);
    float* sb1   = (float*)(smb + 208896);
    float* sb2   = (float*)(smb + 209408);
    float* sattn = (float*)(smb + 209920);   // [2][256]
    int*   sidx  = (int*)(smb + 211968);     // [2][256]

    const int tid = threadIdx.x;
    const int w = tid >> 5, lane = tid & 31;
    const int ar = lane >> 2, ac = lane & 3;
    const int m0 = w * 32;
    const bool is64 = (g_idx_is64 != 0);

    load_w16(sW1, Wn1, tid);
    load_w16(sW2, Wn2, tid);
    if (tid < DIM) { sb1[tid] = bn1[tid]; sb2[tid] = bn2[tid]; }

    const int ntiles = (N + AT - 1) / AT;
    const int t0 = blockIdx.x;

    // prologue: tile t0 into buffer 0
    {
        int base = t0 * AT;
        load_x16<AT>(sx0, x, base, N, tid);
        int node = base + tid;
        if (node < N) {
            int id = load_index(idxp, node, is64);
            sidx[tid] = id;
            sattn[tid] = __fdividef(g_gate[node], g_segsum[id]);
        } else { sidx[tid] = SEG_SENT; sattn[tid] = 0.0f; }
    }
    __syncthreads();

    int p = 0;
    for (int tile = t0; tile < ntiles; tile += AGRID, p ^= 1) {
        const __half* cur = p ? sx1 : sx0;
        __half*       nxt = p ? sx0 : sx1;
        const float* acur = sattn + p * 256;
        const int*   icur = sidx + p * 256;
        float*       anxt = sattn + (p ^ 1) * 256;
        int*         inxt = sidx + (p ^ 1) * 256;

        // GEMM1: u = x @ W1
        float acc[2][16][4];
        #pragma unroll
        for (int mi = 0; mi < 2; ++mi)
            #pragma unroll
            for (int j = 0; j < 16; ++j)
                #pragma unroll
                for (int c = 0; c < 4; ++c) acc[mi][j][c] = 0.0f;
        warp_gemm_fn(cur, sW1, acc, m0, lane);

        // t = half(silu(u + b1)) packed into A-fragments (registers only)
        uint32_t tf[2][16][2];
        #pragma unroll
        for (int mi = 0; mi < 2; ++mi)
            #pragma unroll
            for (int j = 0; j < 16; ++j) {
                int c = 8 * j + 2 * ac;
                float u0 = sb1[c], u1 = sb1[c + 1];
                tf[mi][j][0] = pack_half2(silu_f(acc[mi][j][0] + u0),
                                          silu_f(acc[mi][j][1] + u1));
                tf[mi][j][1] = pack_half2(silu_f(acc[mi][j][2] + u0),
                                          silu_f(acc[mi][j][3] + u1));
            }

        // prefetch next tile while GEMM2/scatter run (acc regs free here)
        int ntile = tile + AGRID;
        if (ntile < ntiles) {
            int nbase = ntile * AT;
            load_x16<AT>(nxt, x, nbase, N, tid);
            int node = nbase + tid;
            if (node < N) {
                int id = load_index(idxp, node, is64);
                inxt[tid] = id;
                anxt[tid] = __fdividef(g_gate[node], g_segsum[id]);
            } else { inxt[tid] = SEG_SENT; anxt[tid] = 0.0f; }
        }

        // GEMM2: h = t @ W2 (A from registers)
        #pragma unroll
        for (int mi = 0; mi < 2; ++mi)
            #pragma unroll
            for (int j = 0; j < 16; ++j)
                #pragma unroll
                for (int c = 0; c < 4; ++c) acc[mi][j][c] = 0.0f;
        warp_gemm_t(tf, sW2, acc, lane);

        // direct-from-accumulator segmented scatter (rows m0..m0+31, sorted segs)
        {
            const float a0 = acur[m0 + ar],      a1 = acur[m0 + ar + 8];
            const float a2 = acur[m0 + ar + 16], a3 = acur[m0 + ar + 24];
            const int   i0 = icur[m0 + ar],      i1 = icur[m0 + ar + 8];
            const int   i2 = icur[m0 + ar + 16], i3 = icur[m0 + ar + 24];
            int seg = icur[m0];
            const int send = icur[m0 + 31];
            while (true) {
                float w0 = (i0 == seg) ? a0 : 0.0f;
                float w1 = (i1 == seg) ? a1 : 0.0f;
                float w2 = (i2 == seg) ? a2 : 0.0f;
                float w3 = (i3 == seg) ? a3 : 0.0f;
                float wsum = w0 + w1 + w2 + w3;
                #pragma unroll
                for (int j = 0; j < 16; ++j) {
                    int c = 8 * j + 2 * ac;
                    float s0 = w0 * acc[0][j][0] + w1 * acc[0][j][2]
                             + w2 * acc[1][j][0] + w3 * acc[1][j][2] + wsum * sb2[c];
                    float s1 = w0 * acc[0][j][1] + w1 * acc[0][j][3]
                             + w2 * acc[1][j][1] + w3 * acc[1][j][3] + wsum * sb2[c + 1];
                    s0 += __shfl_xor_sync(0xffffffffu, s0, 4);
                    s0 += __shfl_xor_sync(0xffffffffu, s0, 8);
                    s0 += __shfl_xor_sync(0xffffffffu, s0, 16);
                    s1 += __shfl_xor_sync(0xffffffffu, s1, 4);
                    s1 += __shfl_xor_sync(0xffffffffu, s1, 8);
                    s1 += __shfl_xor_sync(0xffffffffu, s1, 16);
                    if (ar == 0 && seg != SEG_SENT) {
                        atomicAdd(&out[seg * DIM + c], s0);
                        atomicAdd(&out[seg * DIM + c + 1], s1);
                    }
                }
                if (seg >= send) break;
                int c0 = (i0 > seg) ? i0 : SEG_SENT;
                int c1 = (i1 > seg) ? i1 : SEG_SENT;
                int c2 = (i2 > seg) ? i2 : SEG_SENT;
                int c3 = (i3 > seg) ? i3 : SEG_SENT;
                int nx = min(min(c0, c1), min(c2, c3));
                #pragma unroll
                for (int off = 16; off; off >>= 1)
                    nx = min(nx, __shfl_xor_sync(0xffffffffu, nx, off));
                seg = nx;
            }
        }
        __syncthreads();   // all tile-i reads of cur done; next buffer fully written
    }
}

// ---------------- launch ----------------
extern "C" void kernel_launch(void* const* d_in, const int* in_sizes, int n_in,
                              void* d_out, int out_size) {
    const float* x   = (const float*)d_in[0];
    const void*  idx = d_in[1];
    const float* Wg1 = (const float*)d_in[3];
    const float* bg1 = (const float*)d_in[4];
    const float* Wg2 = (const float*)d_in[5];
    const float* bg2 = (const float*)d_in[6];
    const float* Wn1 = (const float*)d_in[7];
    const float* bn1 = (const float*)d_in[8];
    const float* Wn2 = (const float*)d_in[9];
    const float* bn2 = (const float*)d_in[10];
    float* out = (float*)d_out;

    const int N = in_sizes[0] / DIM;
    const int S = out_size / DIM;

    cudaFuncSetAttribute(gate_kernel, cudaFuncAttributeMaxDynamicSharedMemorySize, G_SMEM_BYTES);
    cudaFuncSetAttribute(agg_kernel,  cudaFuncAttributeMaxDynamicSharedMemorySize, A_SMEM_BYTES);

    di_kernel<<<32, 256>>>((const int*)idx, N, S);

    gate_kernel<<<296, NT, G_SMEM_BYTES>>>(x, idx, Wg1, bg1, Wg2, bg2, N);

    softmax_kernel<<<(N + 255) / 256, 256>>>(idx, N, out, out_size);

    agg_kernel<<<AGRID, NT, A_SMEM_BYTES>>>(x, idx, Wn1, bn1, Wn2, bn2, out, N);
}

// round 14
// speedup vs baseline: 1.1376x; 1.1376x over previous
#include <cuda_runtime.h>
#include <cuda_fp16.h>
#include <stdint.h>

#define DIM 128
#define TILE 128
#define NT 256
#define SH 136     // half stride: word-stride 68 = 4 mod 32 -> conflict-free LDS/LDSM
#define SEG_SENT 0x7FFFFFFF
#define MAXN 1100000
#define MAXSEG 8192

// ---------------- scratch ----------------
__device__ float g_gate[MAXN];        // e = exp(g)
__device__ float g_segsum[MAXSEG];
__device__ int   g_idx_is64;

// ---------------- helpers ----------------
__device__ __forceinline__ float silu_f(float a) {
    return __fdividef(a, 1.0f + __expf(-a));
}
__device__ __forceinline__ uint32_t pack_half2(float lo, float hi) {
    uint32_t u; asm("cvt.rn.f16x2.f32 %0, %1, %2;" : "=r"(u) : "f"(hi), "f"(lo)); return u;
}
__device__ __forceinline__ int load_index(const void* p, int i, bool is64) {
    return is64 ? (int)((const long long*)p)[i] : ((const int*)p)[i];
}
__device__ __forceinline__ void mma_f16(float c[4], const uint32_t a[4], uint32_t b0, uint32_t b1) {
    asm volatile(
        "mma.sync.aligned.m16n8k16.row.col.f32.f16.f16.f32 "
        "{%0,%1,%2,%3}, {%4,%5,%6,%7}, {%8,%9}, {%0,%1,%2,%3};"
        : "+f"(c[0]), "+f"(c[1]), "+f"(c[2]), "+f"(c[3])
        : "r"(a[0]), "r"(a[1]), "r"(a[2]), "r"(a[3]), "r"(b0), "r"(b1));
}
__device__ __forceinline__ void ldsm_x4(uint32_t r[4], uint32_t addr) {
    asm volatile("ldmatrix.sync.aligned.m8n8.x4.shared.b16 {%0,%1,%2,%3}, [%4];"
        : "=r"(r[0]), "=r"(r[1]), "=r"(r[2]), "=r"(r[3]) : "r"(addr));
}

// W[k][n] fp32 row-major -> smem transposed half [n*SH + k], MLP-batched
__device__ __forceinline__ void load_w16(__half* swh, const float* __restrict__ W, int tid) {
    #pragma unroll
    for (int b = 0; b < 2; ++b) {
        float4 v[8];
        #pragma unroll
        for (int i = 0; i < 8; ++i) v[i] = ((const float4*)W)[tid + (b * 8 + i) * NT];
        #pragma unroll
        for (int i = 0; i < 8; ++i) {
            int q = tid + (b * 8 + i) * NT;
            int k = q >> 5, nv = (q & 31) * 4;
            swh[(nv + 0) * SH + k] = __float2half_rn(v[i].x);
            swh[(nv + 1) * SH + k] = __float2half_rn(v[i].y);
            swh[(nv + 2) * SH + k] = __float2half_rn(v[i].z);
            swh[(nv + 3) * SH + k] = __float2half_rn(v[i].w);
        }
    }
}

// fp32 128-row tile -> half smem [row*SH + col], MLP-batched (8 LDG.128 in flight)
__device__ __forceinline__ void load_x16(__half* sx, const float* __restrict__ x,
                                         int base, int N, int tid) {
    #pragma unroll
    for (int b = 0; b < 2; ++b) {
        float4 v[8];
        #pragma unroll
        for (int i = 0; i < 8; ++i) {
            int q = tid + (b * 8 + i) * NT;
            int node = base + (q >> 5);
            v[i] = (node < N) ? ((const float4*)x)[(size_t)node * 32 + (q & 31)]
                              : make_float4(0.f, 0.f, 0.f, 0.f);
        }
        #pragma unroll
        for (int i = 0; i < 8; ++i) {
            int q = tid + (b * 8 + i) * NT;
            int n = q >> 5, kv = q & 31;
            uint2 pk;
            pk.x = pack_half2(v[i].x, v[i].y);
            pk.y = pack_half2(v[i].z, v[i].w);
            *(uint2*)&sx[n * SH + kv * 4] = pk;
        }
    }
}

// 32x64 warp-tile GEMM with ldmatrix.x4 operand loads. K=128 in 8 k16 steps.
// acc[mi][j][c]: rows m0+mi*16+{ar,ar+8}, cols n0+8j+{2ac,2ac+1}
__device__ __forceinline__ void warp_gemm16(uint32_t sx_a, uint32_t sW_a,
                                            float acc[2][8][4], int m0, int n0, int lane) {
    const uint32_t aAddr0 = sx_a + (uint32_t)((m0 + (lane & 15)) * SH + ((lane >> 4) << 3)) * 2;
    const uint32_t aAddr1 = aAddr0 + 16 * SH * 2;
    const uint32_t bAddr  = sW_a + (uint32_t)((n0 + ((lane >> 4) << 3) + (lane & 7)) * SH
                                              + (((lane >> 3) & 1) << 3)) * 2;
    #pragma unroll
    for (int ks = 0; ks < 8; ++ks) {
        const uint32_t kb = ks * 32;   // 16 halfs = 32 bytes
        uint32_t a[2][4];
        ldsm_x4(a[0], aAddr0 + kb);
        ldsm_x4(a[1], aAddr1 + kb);
        #pragma unroll
        for (int p = 0; p < 4; ++p) {
            uint32_t b[4];
            ldsm_x4(b, bAddr + (uint32_t)(p * 16 * SH) * 2 + kb);
            mma_f16(acc[0][2 * p],     a[0], b[0], b[1]);
            mma_f16(acc[1][2 * p],     a[1], b[0], b[1]);
            mma_f16(acc[0][2 * p + 1], a[0], b[2], b[3]);
            mma_f16(acc[1][2 * p + 1], a[1], b[2], b[3]);
        }
    }
}

__device__ __forceinline__ void zero_acc(float acc[2][8][4]) {
    #pragma unroll
    for (int mi = 0; mi < 2; ++mi)
        #pragma unroll
        for (int j = 0; j < 8; ++j)
            #pragma unroll
            for (int c = 0; c < 4; ++c) acc[mi][j][c] = 0.0f;
}

// ---------------- detect + init (segsum + out zero) ----------------
__global__ void di_kernel(const int* v, int n, float* out, int out_n, int S) {
    if (blockIdx.x == 0) {
        int p = n - 1 - (int)threadIdx.x;
        int nz = 0;
        if (p >= 0 && (p & 1) && v[p] != 0) nz = 1;
        int any = __syncthreads_or(nz);
        if (threadIdx.x == 0) g_idx_is64 = any ? 0 : 1;
    }
    int i = blockIdx.x * blockDim.x + threadIdx.x;
    int stride = gridDim.x * blockDim.x;
    for (int p = i; p < out_n; p += stride) out[p] = 0.0f;
    for (int p = i; p < S; p += stride) g_segsum[p] = 0.0f;
}

// ---------------- pass 1: fused gate GEMM + exp + segment sum ----------------
// bytes: sW@0(34816) sx@34816(34816) b1@69632(512) w2@70144(512) sg@70656(1024) idx@71680(512)
#define G_SMEM_BYTES 72192

__global__ __launch_bounds__(NT, 2)
void gate_kernel(const float* __restrict__ x, const void* __restrict__ idxp,
                 const float* __restrict__ Wg1, const float* __restrict__ bg1,
                 const float* __restrict__ Wg2, const float* __restrict__ bg2, int N) {
    extern __shared__ char smb[];
    __half* sW  = (__half*)smb;
    __half* sx  = (__half*)(smb + 34816);
    float* sb1  = (float*)(smb + 69632);
    float* sw2  = (float*)(smb + 70144);
    float* sg   = (float*)(smb + 70656);
    int*  sidx  = (int*)(smb + 71680);
    const uint32_t sW_a = (uint32_t)__cvta_generic_to_shared(sW);
    const uint32_t sx_a = (uint32_t)__cvta_generic_to_shared(sx);

    const int tid = threadIdx.x;
    const int w = tid >> 5, lane = tid & 31;
    const int ac = lane & 3;
    const int mq = w & 3, nh = w >> 2;
    const bool is64 = (g_idx_is64 != 0);

    load_w16(sW, Wg1, tid);
    if (tid < DIM) { sb1[tid] = bg1[tid]; sw2[tid] = Wg2[tid]; }
    const float bg2v = bg2[0];
    __syncthreads();

    const int ntiles = (N + TILE - 1) / TILE;
    for (int tile = blockIdx.x; tile < ntiles; tile += gridDim.x) {
        const int base = tile * TILE;

        load_x16(sx, x, base, N, tid);
        if (tid < TILE) {
            int node = base + tid;
            sidx[tid] = (node < N) ? load_index(idxp, node, is64) : -1;
        }
        __syncthreads();

        float acc[2][8][4];
        zero_acc(acc);
        warp_gemm16(sx_a, sW_a, acc, mq * 32, nh * 64, lane);

        // partial silu-dot over this warp's 64 cols, per row
        const int ar = lane >> 2;
        #pragma unroll
        for (int mi = 0; mi < 2; ++mi) {
            float p0 = 0.0f, p1 = 0.0f;
            #pragma unroll
            for (int j = 0; j < 8; ++j) {
                int c = nh * 64 + 8 * j + 2 * ac;
                float s0 = sw2[c], s1 = sw2[c + 1];
                float u0 = sb1[c], u1 = sb1[c + 1];
                p0 = fmaf(silu_f(acc[mi][j][0] + u0), s0, p0);
                p0 = fmaf(silu_f(acc[mi][j][1] + u1), s1, p0);
                p1 = fmaf(silu_f(acc[mi][j][2] + u0), s0, p1);
                p1 = fmaf(silu_f(acc[mi][j][3] + u1), s1, p1);
            }
            p0 += __shfl_xor_sync(0xffffffffu, p0, 1);
            p0 += __shfl_xor_sync(0xffffffffu, p0, 2);
            p1 += __shfl_xor_sync(0xffffffffu, p1, 1);
            p1 += __shfl_xor_sync(0xffffffffu, p1, 2);
            if (ac == 0) {
                int r = mq * 32 + mi * 16 + ar;
                sg[nh * 128 + r] = p0;
                sg[nh * 128 + r + 8] = p1;
            }
        }
        __syncthreads();

        // e = exp(g) (unstabilized — |g| is small; exact same attn mathematically),
        // store e, warp-segmented SUM -> atomicAdd segsum
        if (tid < TILE) {
            float g = sg[tid] + sg[128 + tid] + bg2v;
            float e = __expf(g);
            int node = base + tid;
            if (node < N) g_gate[node] = e;
            int id = sidx[tid];
            float v = (id >= 0) ? e : 0.0f;
            #pragma unroll
            for (int off = 1; off < 32; off <<= 1) {
                float ov = __shfl_down_sync(0xffffffffu, v, off);
                int  oid = __shfl_down_sync(0xffffffffu, id, off);
                if (lane + off < 32 && oid == id) v += ov;
            }
            int pid = __shfl_up_sync(0xffffffffu, id, 1);
            if (((lane == 0) || (pid != id)) && id >= 0) atomicAdd(&g_segsum[id], v);
        }
        __syncthreads();
    }
}

// ---------------- pass 2: persistent node MLP + direct-from-acc scatter ----------------
// bytes: sW1@0(34816) sW2@34816(34816) sx@69632(34816)
//        b1@104448(512) b2@104960(512) attn@105472(512) idx@105984(512)
#define A_SMEM_BYTES 106496

__global__ __launch_bounds__(NT, 2)
void agg_kernel(const float* __restrict__ x, const void* __restrict__ idxp,
                const float* __restrict__ Wn1, const float* __restrict__ bn1,
                const float* __restrict__ Wn2, const float* __restrict__ bn2,
                float* __restrict__ out, int N) {
    extern __shared__ char smb[];
    __half* sW1  = (__half*)smb;
    __half* sW2  = (__half*)(smb + 34816);
    __half* sx   = (__half*)(smb + 69632);
    float* sb1   = (float*)(smb + 104448);
    float* sb2   = (float*)(smb + 104960);
    float* sattn = (float*)(smb + 105472);
    int*   sidx  = (int*)(smb + 105984);
    const uint32_t sW1_a = (uint32_t)__cvta_generic_to_shared(sW1);
    const uint32_t sW2_a = (uint32_t)__cvta_generic_to_shared(sW2);
    const uint32_t sx_a  = (uint32_t)__cvta_generic_to_shared(sx);

    const int tid = threadIdx.x;
    const int w = tid >> 5, lane = tid & 31;
    const int ar = lane >> 2, ac = lane & 3;
    const int mq = w & 3, nh = w >> 2;
    const bool is64 = (g_idx_is64 != 0);

    load_w16(sW1, Wn1, tid);
    load_w16(sW2, Wn2, tid);
    if (tid < DIM) { sb1[tid] = bn1[tid]; sb2[tid] = bn2[tid]; }
    __syncthreads();

    const int ntiles = (N + TILE - 1) / TILE;
    for (int tile = blockIdx.x; tile < ntiles; tile += gridDim.x) {
        const int base = tile * TILE;

        load_x16(sx, x, base, N, tid);
        if (tid < TILE) {
            int node = base + tid;
            if (node < N) {
                int id = load_index(idxp, node, is64);
                sidx[tid] = id;
                sattn[tid] = __fdividef(g_gate[node], g_segsum[id]);
            } else { sidx[tid] = SEG_SENT; sattn[tid] = 0.0f; }
        }
        __syncthreads();

        // GEMM1: x @ W1
        float acc[2][8][4];
        zero_acc(acc);
        warp_gemm16(sx_a, sW1_a, acc, mq * 32, nh * 64, lane);
        __syncthreads();   // all warps done reading x

        // t = half(silu(acc + b1)) -> own (row,col) region of sx
        #pragma unroll
        for (int mi = 0; mi < 2; ++mi) {
            int r0 = mq * 32 + mi * 16 + ar;
            #pragma unroll
            for (int j = 0; j < 8; ++j) {
                int c = nh * 64 + 8 * j + 2 * ac;
                float t00 = silu_f(acc[mi][j][0] + sb1[c]);
                float t01 = silu_f(acc[mi][j][1] + sb1[c + 1]);
                float t10 = silu_f(acc[mi][j][2] + sb1[c]);
                float t11 = silu_f(acc[mi][j][3] + sb1[c + 1]);
                *(uint32_t*)&sx[r0 * SH + c] = pack_half2(t00, t01);
                *(uint32_t*)&sx[(r0 + 8) * SH + c] = pack_half2(t10, t11);
            }
        }
        __syncthreads();

        // GEMM2: t @ W2
        zero_acc(acc);
        warp_gemm16(sx_a, sW2_a, acc, mq * 32, nh * 64, lane);

        // direct-from-accumulator segmented scatter (rows m0..m0+31 sorted)
        {
            const int m0 = mq * 32;
            const float a0 = sattn[m0 + ar],      a1 = sattn[m0 + ar + 8];
            const float a2 = sattn[m0 + ar + 16], a3 = sattn[m0 + ar + 24];
            const int   i0 = sidx[m0 + ar],       i1 = sidx[m0 + ar + 8];
            const int   i2 = sidx[m0 + ar + 16],  i3 = sidx[m0 + ar + 24];
            int seg = sidx[m0];
            const int send = sidx[m0 + 31];
            while (true) {
                float w0 = (i0 == seg) ? a0 : 0.0f;
                float w1 = (i1 == seg) ? a1 : 0.0f;
                float w2 = (i2 == seg) ? a2 : 0.0f;
                float w3 = (i3 == seg) ? a3 : 0.0f;
                float wsum = w0 + w1 + w2 + w3;
                #pragma unroll
                for (int j = 0; j < 8; ++j) {
                    int c = nh * 64 + 8 * j + 2 * ac;
                    float s0 = w0 * acc[0][j][0] + w1 * acc[0][j][2]
                             + w2 * acc[1][j][0] + w3 * acc[1][j][2] + wsum * sb2[c];
                    float s1 = w0 * acc[0][j][1] + w1 * acc[0][j][3]
                             + w2 * acc[1][j][1] + w3 * acc[1][j][3] + wsum * sb2[c + 1];
                    s0 += __shfl_xor_sync(0xffffffffu, s0, 4);
                    s0 += __shfl_xor_sync(0xffffffffu, s0, 8);
                    s0 += __shfl_xor_sync(0xffffffffu, s0, 16);
                    s1 += __shfl_xor_sync(0xffffffffu, s1, 4);
                    s1 += __shfl_xor_sync(0xffffffffu, s1, 8);
                    s1 += __shfl_xor_sync(0xffffffffu, s1, 16);
                    if (ar == 0 && seg != SEG_SENT) {
                        atomicAdd(&out[seg * DIM + c], s0);
                        atomicAdd(&out[seg * DIM + c + 1], s1);
                    }
                }
                if (seg >= send) break;
                int c0 = (i0 > seg) ? i0 : SEG_SENT;
                int c1 = (i1 > seg) ? i1 : SEG_SENT;
                int c2 = (i2 > seg) ? i2 : SEG_SENT;
                int c3 = (i3 > seg) ? i3 : SEG_SENT;
                int nx = min(min(c0, c1), min(c2, c3));
                #pragma unroll
                for (int off = 16; off; off >>= 1)
                    nx = min(nx, __shfl_xor_sync(0xffffffffu, nx, off));
                seg = nx;
            }
        }
        __syncthreads();
    }
}

// ---------------- launch ----------------
extern "C" void kernel_launch(void* const* d_in, const int* in_sizes, int n_in,
                              void* d_out, int out_size) {
    const float* x   = (const float*)d_in[0];
    const void*  idx = d_in[1];
    const float* Wg1 = (const float*)d_in[3];
    const float* bg1 = (const float*)d_in[4];
    const float* Wg2 = (const float*)d_in[5];
    const float* bg2 = (const float*)d_in[6];
    const float* Wn1 = (const float*)d_in[7];
    const float* bn1 = (const float*)d_in[8];
    const float* Wn2 = (const float*)d_in[9];
    const float* bn2 = (const float*)d_in[10];
    float* out = (float*)d_out;

    const int N = in_sizes[0] / DIM;
    const int S = out_size / DIM;

    cudaFuncSetAttribute(gate_kernel, cudaFuncAttributeMaxDynamicSharedMemorySize, G_SMEM_BYTES);
    cudaFuncSetAttribute(agg_kernel,  cudaFuncAttributeMaxDynamicSharedMemorySize, A_SMEM_BYTES);

    di_kernel<<<256, 256>>>((const int*)idx, N, out, out_size, S);

    gate_kernel<<<296, NT, G_SMEM_BYTES>>>(x, idx, Wg1, bg1, Wg2, bg2, N);

    agg_kernel<<<296, NT, A_SMEM_BYTES>>>(x, idx, Wn1, bn1, Wn2, bn2, out, N);
}

// round 15
// speedup vs baseline: 1.2083x; 1.0622x over previous
#include <cuda_runtime.h>
#include <cuda_fp16.h>
#include <stdint.h>

#define DIM 128
#define TILE 256
#define NT 512
#define SH 136     // half stride: word-stride 68 = 4 mod 32 -> conflict-free LDS/LDSM
#define SEG_SENT 0x7FFFFFFF
#define MAXSEG 8192
#define GRID_F 152

// ---------------- scratch ----------------
__device__ float g_segsum[MAXSEG];
__device__ int   g_idx_is64;

// ---------------- helpers ----------------
__device__ __forceinline__ float silu_f(float a) {
    return __fdividef(a, 1.0f + __expf(-a));
}
__device__ __forceinline__ uint32_t pack_half2(float lo, float hi) {
    uint32_t u; asm("cvt.rn.f16x2.f32 %0, %1, %2;" : "=r"(u) : "f"(hi), "f"(lo)); return u;
}
__device__ __forceinline__ int load_index(const void* p, int i, bool is64) {
    return is64 ? (int)((const long long*)p)[i] : ((const int*)p)[i];
}
__device__ __forceinline__ void mma_f16(float c[4], const uint32_t a[4], uint32_t b0, uint32_t b1) {
    asm volatile(
        "mma.sync.aligned.m16n8k16.row.col.f32.f16.f16.f32 "
        "{%0,%1,%2,%3}, {%4,%5,%6,%7}, {%8,%9}, {%0,%1,%2,%3};"
        : "+f"(c[0]), "+f"(c[1]), "+f"(c[2]), "+f"(c[3])
        : "r"(a[0]), "r"(a[1]), "r"(a[2]), "r"(a[3]), "r"(b0), "r"(b1));
}
__device__ __forceinline__ void ldsm_x4(uint32_t r[4], uint32_t addr) {
    asm volatile("ldmatrix.sync.aligned.m8n8.x4.shared.b16 {%0,%1,%2,%3}, [%4];"
        : "=r"(r[0]), "=r"(r[1]), "=r"(r[2]), "=r"(r[3]) : "r"(addr));
}

// W[k][n] fp32 row-major -> smem transposed half [n*SH + k], MLP-batched (512 thr)
__device__ __forceinline__ void load_w16(__half* swh, const float* __restrict__ W, int tid) {
    float4 v[8];
    #pragma unroll
    for (int i = 0; i < 8; ++i) v[i] = ((const float4*)W)[tid + i * NT];
    #pragma unroll
    for (int i = 0; i < 8; ++i) {
        int q = tid + i * NT;
        int k = q >> 5, nv = (q & 31) * 4;
        swh[(nv + 0) * SH + k] = __float2half_rn(v[i].x);
        swh[(nv + 1) * SH + k] = __float2half_rn(v[i].y);
        swh[(nv + 2) * SH + k] = __float2half_rn(v[i].z);
        swh[(nv + 3) * SH + k] = __float2half_rn(v[i].w);
    }
}

// fp32 256-row tile -> half smem [row*SH + col], MLP-batched (8 LDG.128 in flight, 512 thr)
__device__ __forceinline__ void load_x16(__half* sx, const float* __restrict__ x,
                                         int base, int N, int tid) {
    #pragma unroll
    for (int b = 0; b < 2; ++b) {
        float4 v[8];
        #pragma unroll
        for (int i = 0; i < 8; ++i) {
            int q = tid + (b * 8 + i) * NT;
            int node = base + (q >> 5);
            v[i] = (node < N) ? ((const float4*)x)[(size_t)node * 32 + (q & 31)]
                              : make_float4(0.f, 0.f, 0.f, 0.f);
        }
        #pragma unroll
        for (int i = 0; i < 8; ++i) {
            int q = tid + (b * 8 + i) * NT;
            int n = q >> 5, kv = q & 31;
            uint2 pk;
            pk.x = pack_half2(v[i].x, v[i].y);
            pk.y = pack_half2(v[i].z, v[i].w);
            *(uint2*)&sx[n * SH + kv * 4] = pk;
        }
    }
}

// 32x64 warp-tile GEMM with ldmatrix.x4. K=128 in 8 k16 steps.
// acc[mi][j][c]: rows m0+mi*16+{ar,ar+8}, cols n0+8j+{2ac,2ac+1}
__device__ __forceinline__ void warp_gemm16(uint32_t sx_a, uint32_t sW_a,
                                            float acc[2][8][4], int m0, int n0, int lane) {
    const uint32_t aAddr0 = sx_a + (uint32_t)((m0 + (lane & 15)) * SH + ((lane >> 4) << 3)) * 2;
    const uint32_t aAddr1 = aAddr0 + 16 * SH * 2;
    const uint32_t bAddr  = sW_a + (uint32_t)((n0 + ((lane >> 4) << 3) + (lane & 7)) * SH
                                              + (((lane >> 3) & 1) << 3)) * 2;
    #pragma unroll
    for (int ks = 0; ks < 8; ++ks) {
        const uint32_t kb = ks * 32;
        uint32_t a[2][4];
        ldsm_x4(a[0], aAddr0 + kb);
        ldsm_x4(a[1], aAddr1 + kb);
        #pragma unroll
        for (int p = 0; p < 4; ++p) {
            uint32_t b[4];
            ldsm_x4(b, bAddr + (uint32_t)(p * 16 * SH) * 2 + kb);
            mma_f16(acc[0][2 * p],     a[0], b[0], b[1]);
            mma_f16(acc[1][2 * p],     a[1], b[0], b[1]);
            mma_f16(acc[0][2 * p + 1], a[0], b[2], b[3]);
            mma_f16(acc[1][2 * p + 1], a[1], b[2], b[3]);
        }
    }
}

__device__ __forceinline__ void zero_acc(float acc[2][8][4]) {
    #pragma unroll
    for (int mi = 0; mi < 2; ++mi)
        #pragma unroll
        for (int j = 0; j < 8; ++j)
            #pragma unroll
            for (int c = 0; c < 4; ++c) acc[mi][j][c] = 0.0f;
}

// ---------------- detect + init (segsum + out zero) ----------------
__global__ void di_kernel(const int* v, int n, float* out, int out_n, int S) {
    if (blockIdx.x == 0) {
        int p = n - 1 - (int)threadIdx.x;
        int nz = 0;
        if (p >= 0 && (p & 1) && v[p] != 0) nz = 1;
        int any = __syncthreads_or(nz);
        if (threadIdx.x == 0) g_idx_is64 = any ? 0 : 1;
    }
    int i = blockIdx.x * blockDim.x + threadIdx.x;
    int stride = gridDim.x * blockDim.x;
    for (int p = i; p < out_n; p += stride) out[p] = 0.0f;
    for (int p = i; p < S; p += stride) g_segsum[p] = 0.0f;
}

// ---------------- final normalize: out[s][c] /= segsum[s] ----------------
__global__ void norm_kernel(float* __restrict__ out, int out_n) {
    int i = blockIdx.x * blockDim.x + threadIdx.x;
    if (i < out_n) {
        float s = g_segsum[i >> 7];
        out[i] = (s > 0.0f) ? out[i] * __frcp_rn(s) : 0.0f;
    }
}

// ---------------- fused: gate GEMM + exp + segsum + node MLP + e-weighted scatter ----------------
// bytes: sWg@0(34816) sW1@34816 sW2@69632 sx@104448(69632)
//        b1g@174080(512) w2g@174592(512) b1n@175104(512) b2n@175616(512)
//        se@176128(1024) sg@177152(2048) idx@179200(1024)
#define F_SMEM_BYTES 180224

__global__ __launch_bounds__(NT, 1)
void fused_kernel(const float* __restrict__ x, const void* __restrict__ idxp,
                  const float* __restrict__ Wg1, const float* __restrict__ bg1,
                  const float* __restrict__ Wg2, const float* __restrict__ bg2,
                  const float* __restrict__ Wn1, const float* __restrict__ bn1,
                  const float* __restrict__ Wn2, const float* __restrict__ bn2,
                  float* __restrict__ out, int N) {
    extern __shared__ char smb[];
    __half* sWg  = (__half*)smb;
    __half* sW1  = (__half*)(smb + 34816);
    __half* sW2  = (__half*)(smb + 69632);
    __half* sx   = (__half*)(smb + 104448);
    float* sb1g  = (float*)(smb + 174080);
    float* sw2g  = (float*)(smb + 174592);
    float* sb1n  = (float*)(smb + 175104);
    float* sb2n  = (float*)(smb + 175616);
    float* se    = (float*)(smb + 176128);   // e per row (256)
    float* sg    = (float*)(smb + 177152);   // gate partials [2][256]
    int*   sidx  = (int*)(smb + 179200);     // 256
    const uint32_t sWg_a = (uint32_t)__cvta_generic_to_shared(sWg);
    const uint32_t sW1_a = (uint32_t)__cvta_generic_to_shared(sW1);
    const uint32_t sW2_a = (uint32_t)__cvta_generic_to_shared(sW2);
    const uint32_t sx_a  = (uint32_t)__cvta_generic_to_shared(sx);

    const int tid = threadIdx.x;
    const int w = tid >> 5, lane = tid & 31;
    const int ar = lane >> 2, ac = lane & 3;
    const int mq = w & 7, nh = w >> 3;       // 32-row block, 64-col half
    const int m0 = mq * 32, n0 = nh * 64;
    const bool is64 = (g_idx_is64 != 0);

    load_w16(sWg, Wg1, tid);
    load_w16(sW1, Wn1, tid);
    load_w16(sW2, Wn2, tid);
    if (tid < DIM) {
        sb1g[tid] = bg1[tid]; sw2g[tid] = Wg2[tid];
        sb1n[tid] = bn1[tid]; sb2n[tid] = bn2[tid];
    }
    const float bg2v = bg2[0];
    __syncthreads();

    const int ntiles = (N + TILE - 1) / TILE;
    for (int tile = blockIdx.x; tile < ntiles; tile += GRID_F) {
        const int base = tile * TILE;

        load_x16(sx, x, base, N, tid);
        if (tid < TILE) {
            int node = base + tid;
            sidx[tid] = (node < N) ? load_index(idxp, node, is64) : SEG_SENT;
        }
        __syncthreads();

        float acc[2][8][4];

        // ---- gate GEMM: x @ Wg1 ----
        zero_acc(acc);
        warp_gemm16(sx_a, sWg_a, acc, m0, n0, lane);

        // partial silu-dot over this warp's 64 cols, per row
        #pragma unroll
        for (int mi = 0; mi < 2; ++mi) {
            float p0 = 0.0f, p1 = 0.0f;
            #pragma unroll
            for (int j = 0; j < 8; ++j) {
                int c = n0 + 8 * j + 2 * ac;
                float s0 = sw2g[c], s1 = sw2g[c + 1];
                float u0 = sb1g[c], u1 = sb1g[c + 1];
                p0 = fmaf(silu_f(acc[mi][j][0] + u0), s0, p0);
                p0 = fmaf(silu_f(acc[mi][j][1] + u1), s1, p0);
                p1 = fmaf(silu_f(acc[mi][j][2] + u0), s0, p1);
                p1 = fmaf(silu_f(acc[mi][j][3] + u1), s1, p1);
            }
            p0 += __shfl_xor_sync(0xffffffffu, p0, 1);
            p0 += __shfl_xor_sync(0xffffffffu, p0, 2);
            p1 += __shfl_xor_sync(0xffffffffu, p1, 1);
            p1 += __shfl_xor_sync(0xffffffffu, p1, 2);
            if (ac == 0) {
                int r = m0 + mi * 16 + ar;
                sg[nh * 256 + r] = p0;
                sg[nh * 256 + r + 8] = p1;
            }
        }
        __syncthreads();

        // e = exp(g) (unstabilized, exact attn after deferred normalize);
        // warp-segmented SUM (rows sorted) -> atomicAdd segsum; keep e in smem
        if (tid < TILE) {
            float g = sg[tid] + sg[256 + tid] + bg2v;
            float e = __expf(g);
            int id = sidx[tid];
            if (id == SEG_SENT) e = 0.0f;
            se[tid] = e;
            float v = e;
            #pragma unroll
            for (int off = 1; off < 32; off <<= 1) {
                float ov = __shfl_down_sync(0xffffffffu, v, off);
                int  oid = __shfl_down_sync(0xffffffffu, id, off);
                if (lane + off < 32 && oid == id) v += ov;
            }
            int pid = __shfl_up_sync(0xffffffffu, id, 1);
            if (((lane == 0) || (pid != id)) && id != SEG_SENT) atomicAdd(&g_segsum[id], v);
        }

        // ---- GEMM1: x @ Wn1 (x still resident; no barrier needed — gate GEMM
        //      read x and nothing wrote it) ----
        zero_acc(acc);
        warp_gemm16(sx_a, sW1_a, acc, m0, n0, lane);
        __syncthreads();   // all warps done reading x; se/sg writes visible

        // t = half(silu(acc + b1n)) -> own (row,col) region of sx
        #pragma unroll
        for (int mi = 0; mi < 2; ++mi) {
            int r0 = m0 + mi * 16 + ar;
            #pragma unroll
            for (int j = 0; j < 8; ++j) {
                int c = n0 + 8 * j + 2 * ac;
                float t00 = silu_f(acc[mi][j][0] + sb1n[c]);
                float t01 = silu_f(acc[mi][j][1] + sb1n[c + 1]);
                float t10 = silu_f(acc[mi][j][2] + sb1n[c]);
                float t11 = silu_f(acc[mi][j][3] + sb1n[c + 1]);
                *(uint32_t*)&sx[r0 * SH + c] = pack_half2(t00, t01);
                *(uint32_t*)&sx[(r0 + 8) * SH + c] = pack_half2(t10, t11);
            }
        }
        __syncthreads();

        // ---- GEMM2: t @ Wn2 ----
        zero_acc(acc);
        warp_gemm16(sx_a, sW2_a, acc, m0, n0, lane);

        // e-weighted direct-from-accumulator segmented scatter (unnormalized)
        {
            const float a0 = se[m0 + ar],      a1 = se[m0 + ar + 8];
            const float a2 = se[m0 + ar + 16], a3 = se[m0 + ar + 24];
            const int   i0 = sidx[m0 + ar],    i1 = sidx[m0 + ar + 8];
            const int   i2 = sidx[m0 + ar + 16], i3 = sidx[m0 + ar + 24];
            int seg = sidx[m0];
            const int send = sidx[m0 + 31];
            while (true) {
                float w0 = (i0 == seg) ? a0 : 0.0f;
                float w1 = (i1 == seg) ? a1 : 0.0f;
                float w2 = (i2 == seg) ? a2 : 0.0f;
                float w3 = (i3 == seg) ? a3 : 0.0f;
                float wsum = w0 + w1 + w2 + w3;
                #pragma unroll
                for (int j = 0; j < 8; ++j) {
                    int c = n0 + 8 * j + 2 * ac;
                    float s0 = w0 * acc[0][j][0] + w1 * acc[0][j][2]
                             + w2 * acc[1][j][0] + w3 * acc[1][j][2] + wsum * sb2n[c];
                    float s1 = w0 * acc[0][j][1] + w1 * acc[0][j][3]
                             + w2 * acc[1][j][1] + w3 * acc[1][j][3] + wsum * sb2n[c + 1];
                    s0 += __shfl_xor_sync(0xffffffffu, s0, 4);
                    s0 += __shfl_xor_sync(0xffffffffu, s0, 8);
                    s0 += __shfl_xor_sync(0xffffffffu, s0, 16);
                    s1 += __shfl_xor_sync(0xffffffffu, s1, 4);
                    s1 += __shfl_xor_sync(0xffffffffu, s1, 8);
                    s1 += __shfl_xor_sync(0xffffffffu, s1, 16);
                    if (ar == 0 && seg != SEG_SENT) {
                        atomicAdd(&out[seg * DIM + c], s0);
                        atomicAdd(&out[seg * DIM + c + 1], s1);
                    }
                }
                if (seg >= send) break;
                int c0 = (i0 > seg) ? i0 : SEG_SENT;
                int c1 = (i1 > seg) ? i1 : SEG_SENT;
                int c2 = (i2 > seg) ? i2 : SEG_SENT;
                int c3 = (i3 > seg) ? i3 : SEG_SENT;
                int nx = min(min(c0, c1), min(c2, c3));
                #pragma unroll
                for (int off = 16; off; off >>= 1)
                    nx = min(nx, __shfl_xor_sync(0xffffffffu, nx, off));
                seg = nx;
            }
        }
        __syncthreads();
    }
}

// ---------------- launch ----------------
extern "C" void kernel_launch(void* const* d_in, const int* in_sizes, int n_in,
                              void* d_out, int out_size) {
    const float* x   = (const float*)d_in[0];
    const void*  idx = d_in[1];
    const float* Wg1 = (const float*)d_in[3];
    const float* bg1 = (const float*)d_in[4];
    const float* Wg2 = (const float*)d_in[5];
    const float* bg2 = (const float*)d_in[6];
    const float* Wn1 = (const float*)d_in[7];
    const float* bn1 = (const float*)d_in[8];
    const float* Wn2 = (const float*)d_in[9];
    const float* bn2 = (const float*)d_in[10];
    float* out = (float*)d_out;

    const int N = in_sizes[0] / DIM;
    const int S = out_size / DIM;

    cudaFuncSetAttribute(fused_kernel, cudaFuncAttributeMaxDynamicSharedMemorySize, F_SMEM_BYTES);

    di_kernel<<<256, 256>>>((const int*)idx, N, out, out_size, S);

    fused_kernel<<<GRID_F, NT, F_SMEM_BYTES>>>(x, idx, Wg1, bg1, Wg2, bg2,
                                               Wn1, bn1, Wn2, bn2, out, N);

    norm_kernel<<<(out_size + 255) / 256, 256>>>(out, out_size);
}

// round 16
// speedup vs baseline: 1.6775x; 1.3883x over previous
#include <cuda_runtime.h>
#include <cuda_fp16.h>
#include <stdint.h>

#define DIM 128
#define TILE 128
#define NTF 256        // fused kernel threads
#define NTZ 512        // final kernel threads
#define SH 136         // half stride: word-stride 68 = 4 mod 32 -> conflict-free LDS/LDSM
#define SEG_SENT 0x7FFFFFFF
#define MAXSEG 8192
#define GRID_F 304

// ---------------- scratch ----------------
__device__ float g_segsum[MAXSEG];
__device__ int   g_idx_is64;

// ---------------- helpers ----------------
__device__ __forceinline__ float silu_f(float a) {
    return __fdividef(a, 1.0f + __expf(-a));
}
__device__ __forceinline__ uint32_t pack_half2(float lo, float hi) {
    uint32_t u; asm("cvt.rn.f16x2.f32 %0, %1, %2;" : "=r"(u) : "f"(hi), "f"(lo)); return u;
}
__device__ __forceinline__ int load_index(const void* p, int i, bool is64) {
    return is64 ? (int)((const long long*)p)[i] : ((const int*)p)[i];
}
__device__ __forceinline__ void mma_f16(float c[4], const uint32_t a[4], uint32_t b0, uint32_t b1) {
    asm volatile(
        "mma.sync.aligned.m16n8k16.row.col.f32.f16.f16.f32 "
        "{%0,%1,%2,%3}, {%4,%5,%6,%7}, {%8,%9}, {%0,%1,%2,%3};"
        : "+f"(c[0]), "+f"(c[1]), "+f"(c[2]), "+f"(c[3])
        : "r"(a[0]), "r"(a[1]), "r"(a[2]), "r"(a[3]), "r"(b0), "r"(b1));
}
__device__ __forceinline__ void ldsm_x4(uint32_t r[4], uint32_t addr) {
    asm volatile("ldmatrix.sync.aligned.m8n8.x4.shared.b16 {%0,%1,%2,%3}, [%4];"
        : "=r"(r[0]), "=r"(r[1]), "=r"(r[2]), "=r"(r[3]) : "r"(addr));
}

// W[k][n] fp32 row-major -> smem transposed half [n*SH + k], MLP-batched
template<int NT>
__device__ __forceinline__ void load_w16(__half* swh, const float* __restrict__ W, int tid) {
    #pragma unroll
    for (int b = 0; b < (DIM * DIM / 4) / (8 * NT); ++b) {
        float4 v[8];
        #pragma unroll
        for (int i = 0; i < 8; ++i) v[i] = ((const float4*)W)[tid + (b * 8 + i) * NT];
        #pragma unroll
        for (int i = 0; i < 8; ++i) {
            int q = tid + (b * 8 + i) * NT;
            int k = q >> 5, nv = (q & 31) * 4;
            swh[(nv + 0) * SH + k] = __float2half_rn(v[i].x);
            swh[(nv + 1) * SH + k] = __float2half_rn(v[i].y);
            swh[(nv + 2) * SH + k] = __float2half_rn(v[i].z);
            swh[(nv + 3) * SH + k] = __float2half_rn(v[i].w);
        }
    }
}

// fp32 128-row tile -> half smem (256 thr, 8 LDG.128 in flight)
__device__ __forceinline__ void load_x16(__half* sx, const float* __restrict__ x,
                                         int base, int N, int tid) {
    #pragma unroll
    for (int b = 0; b < 2; ++b) {
        float4 v[8];
        #pragma unroll
        for (int i = 0; i < 8; ++i) {
            int q = tid + (b * 8 + i) * NTF;
            int node = base + (q >> 5);
            v[i] = (node < N) ? ((const float4*)x)[(size_t)node * 32 + (q & 31)]
                              : make_float4(0.f, 0.f, 0.f, 0.f);
        }
        #pragma unroll
        for (int i = 0; i < 8; ++i) {
            int q = tid + (b * 8 + i) * NTF;
            int n = q >> 5, kv = q & 31;
            uint2 pk;
            pk.x = pack_half2(v[i].x, v[i].y);
            pk.y = pack_half2(v[i].z, v[i].w);
            *(uint2*)&sx[n * SH + kv * 4] = pk;
        }
    }
}

// 32x64 warp-tile GEMM with ldmatrix.x4. K=128 in 8 k16 steps.
// acc[mi][j][c]: rows m0+mi*16+{ar,ar+8}, cols n0+8j+{2ac,2ac+1}
__device__ __forceinline__ void warp_gemm16(uint32_t sx_a, uint32_t sW_a,
                                            float acc[2][8][4], int m0, int n0, int lane) {
    const uint32_t aAddr0 = sx_a + (uint32_t)((m0 + (lane & 15)) * SH + ((lane >> 4) << 3)) * 2;
    const uint32_t aAddr1 = aAddr0 + 16 * SH * 2;
    const uint32_t bAddr  = sW_a + (uint32_t)((n0 + ((lane >> 4) << 3) + (lane & 7)) * SH
                                              + (((lane >> 3) & 1) << 3)) * 2;
    #pragma unroll
    for (int ks = 0; ks < 8; ++ks) {
        const uint32_t kb = ks * 32;
        uint32_t a[2][4];
        ldsm_x4(a[0], aAddr0 + kb);
        ldsm_x4(a[1], aAddr1 + kb);
        #pragma unroll
        for (int p = 0; p < 4; ++p) {
            uint32_t b[4];
            ldsm_x4(b, bAddr + (uint32_t)(p * 16 * SH) * 2 + kb);
            mma_f16(acc[0][2 * p],     a[0], b[0], b[1]);
            mma_f16(acc[1][2 * p],     a[1], b[0], b[1]);
            mma_f16(acc[0][2 * p + 1], a[0], b[2], b[3]);
            mma_f16(acc[1][2 * p + 1], a[1], b[2], b[3]);
        }
    }
}

__device__ __forceinline__ void zero_acc(float acc[2][8][4]) {
    #pragma unroll
    for (int mi = 0; mi < 2; ++mi)
        #pragma unroll
        for (int j = 0; j < 8; ++j)
            #pragma unroll
            for (int c = 0; c < 4; ++c) acc[mi][j][c] = 0.0f;
}

// ---------------- detect + init (segsum + out zero) ----------------
__global__ void di_kernel(const int* v, int n, float* out, int out_n, int S) {
    if (blockIdx.x == 0) {
        int p = n - 1 - (int)threadIdx.x;
        int nz = 0;
        if (p >= 0 && (p & 1) && v[p] != 0) nz = 1;
        int any = __syncthreads_or(nz);
        if (threadIdx.x == 0) g_idx_is64 = any ? 0 : 1;
    }
    int i = blockIdx.x * blockDim.x + threadIdx.x;
    int stride = gridDim.x * blockDim.x;
    for (int p = i; p < out_n; p += stride) out[p] = 0.0f;
    for (int p = i; p < S; p += stride) g_segsum[p] = 0.0f;
}

// ---------------- fused: gate + exp/segsum + GEMM1 + e-weighted t scatter (U accum) ----------------
// bytes: sWg@0(34816) sW1@34816(34816) sx@69632(34816)
//        b1g@104448(512) w2g@104960(512) b1n@105472(512)
//        sg@105984(1024) se@107008(512) idx@107520(512)
#define F_SMEM_BYTES 108032

__global__ __launch_bounds__(NTF, 2)
void fused_kernel(const float* __restrict__ x, const void* __restrict__ idxp,
                  const float* __restrict__ Wg1, const float* __restrict__ bg1,
                  const float* __restrict__ Wg2, const float* __restrict__ bg2,
                  const float* __restrict__ Wn1, const float* __restrict__ bn1,
                  float* __restrict__ out, int N) {
    extern __shared__ char smb[];
    __half* sWg  = (__half*)smb;
    __half* sW1  = (__half*)(smb + 34816);
    __half* sx   = (__half*)(smb + 69632);
    float* sb1g  = (float*)(smb + 104448);
    float* sw2g  = (float*)(smb + 104960);
    float* sb1n  = (float*)(smb + 105472);
    float* sg    = (float*)(smb + 105984);   // [2][128] gate partials
    float* se    = (float*)(smb + 107008);   // 128
    int*   sidx  = (int*)(smb + 107520);     // 128
    const uint32_t sWg_a = (uint32_t)__cvta_generic_to_shared(sWg);
    const uint32_t sW1_a = (uint32_t)__cvta_generic_to_shared(sW1);
    const uint32_t sx_a  = (uint32_t)__cvta_generic_to_shared(sx);

    const int tid = threadIdx.x;
    const int w = tid >> 5, lane = tid & 31;
    const int ar = lane >> 2, ac = lane & 3;
    const int mq = w & 3, nh = w >> 2;
    const int m0 = mq * 32, n0 = nh * 64;
    const bool is64 = (g_idx_is64 != 0);

    load_w16<NTF>(sWg, Wg1, tid);
    load_w16<NTF>(sW1, Wn1, tid);
    if (tid < DIM) {
        sb1g[tid] = bg1[tid]; sw2g[tid] = Wg2[tid]; sb1n[tid] = bn1[tid];
    }
    const float bg2v = bg2[0];
    __syncthreads();

    const int ntiles = (N + TILE - 1) / TILE;
    for (int tile = blockIdx.x; tile < ntiles; tile += GRID_F) {
        const int base = tile * TILE;

        // sx writes are safe: reaching here implies all warps passed B3 of the
        // previous tile, and all sx reads (gate GEMM + GEMM1) are pre-B2.
        load_x16(sx, x, base, N, tid);
        __syncthreads();                 // B1: tile ready

        // sidx written post-B1 (prev scatter finished); visible at B2/B3
        if (tid < TILE) {
            int node = base + tid;
            sidx[tid] = (node < N) ? load_index(idxp, node, is64) : SEG_SENT;
        }

        float acc[2][8][4];

        // ---- gate GEMM: x @ Wg1 ----
        zero_acc(acc);
        warp_gemm16(sx_a, sWg_a, acc, m0, n0, lane);

        // partial silu-dot over this warp's 64 cols, per row -> sg
        #pragma unroll
        for (int mi = 0; mi < 2; ++mi) {
            float p0 = 0.0f, p1 = 0.0f;
            #pragma unroll
            for (int j = 0; j < 8; ++j) {
                int c = n0 + 8 * j + 2 * ac;
                float s0 = sw2g[c], s1 = sw2g[c + 1];
                float u0 = sb1g[c], u1 = sb1g[c + 1];
                p0 = fmaf(silu_f(acc[mi][j][0] + u0), s0, p0);
                p0 = fmaf(silu_f(acc[mi][j][1] + u1), s1, p0);
                p1 = fmaf(silu_f(acc[mi][j][2] + u0), s0, p1);
                p1 = fmaf(silu_f(acc[mi][j][3] + u1), s1, p1);
            }
            p0 += __shfl_xor_sync(0xffffffffu, p0, 1);
            p0 += __shfl_xor_sync(0xffffffffu, p0, 2);
            p1 += __shfl_xor_sync(0xffffffffu, p1, 1);
            p1 += __shfl_xor_sync(0xffffffffu, p1, 2);
            if (ac == 0) {
                int r = m0 + mi * 16 + ar;
                sg[nh * 128 + r] = p0;
                sg[nh * 128 + r + 8] = p1;
            }
        }

        // ---- GEMM1: x @ Wn1 (independent of gate epilogue; fills issue slots) ----
        zero_acc(acc);
        warp_gemm16(sx_a, sW1_a, acc, m0, n0, lane);
        __syncthreads();                 // B2: sg visible; all sx reads done

        // e = exp(g); warp-segmented sum (sorted rows) -> segsum atomics; keep e
        if (tid < TILE) {
            float g = sg[tid] + sg[128 + tid] + bg2v;
            float e = __expf(g);
            int id = sidx[tid];
            if (id == SEG_SENT) e = 0.0f;
            se[tid] = e;
            float v = e;
            #pragma unroll
            for (int off = 1; off < 32; off <<= 1) {
                float ov = __shfl_down_sync(0xffffffffu, v, off);
                int  oid = __shfl_down_sync(0xffffffffu, id, off);
                if (lane + off < 32 && oid == id) v += ov;
            }
            int pid = __shfl_up_sync(0xffffffffu, id, 1);
            if (((lane == 0) || (pid != id)) && id != SEG_SENT) atomicAdd(&g_segsum[id], v);
        }
        __syncthreads();                 // B3: se visible

        // t = silu(acc + b1n) in place (fp32, never leaves registers)
        #pragma unroll
        for (int mi = 0; mi < 2; ++mi)
            #pragma unroll
            for (int j = 0; j < 8; ++j) {
                int c = n0 + 8 * j + 2 * ac;
                float u0 = sb1n[c], u1 = sb1n[c + 1];
                acc[mi][j][0] = silu_f(acc[mi][j][0] + u0);
                acc[mi][j][1] = silu_f(acc[mi][j][1] + u1);
                acc[mi][j][2] = silu_f(acc[mi][j][2] + u0);
                acc[mi][j][3] = silu_f(acc[mi][j][3] + u1);
            }

        // e-weighted segmented row-sum of t -> atomicAdd into out (U accumulation)
        {
            const float a0 = se[m0 + ar],      a1 = se[m0 + ar + 8];
            const float a2 = se[m0 + ar + 16], a3 = se[m0 + ar + 24];
            const int   i0 = sidx[m0 + ar],    i1 = sidx[m0 + ar + 8];
            const int   i2 = sidx[m0 + ar + 16], i3 = sidx[m0 + ar + 24];
            int seg = sidx[m0];
            const int send = sidx[m0 + 31];
            while (true) {
                float w0 = (i0 == seg) ? a0 : 0.0f;
                float w1 = (i1 == seg) ? a1 : 0.0f;
                float w2 = (i2 == seg) ? a2 : 0.0f;
                float w3 = (i3 == seg) ? a3 : 0.0f;
                #pragma unroll
                for (int j = 0; j < 8; ++j) {
                    int c = n0 + 8 * j + 2 * ac;
                    float s0 = w0 * acc[0][j][0] + w1 * acc[0][j][2]
                             + w2 * acc[1][j][0] + w3 * acc[1][j][2];
                    float s1 = w0 * acc[0][j][1] + w1 * acc[0][j][3]
                             + w2 * acc[1][j][1] + w3 * acc[1][j][3];
                    s0 += __shfl_xor_sync(0xffffffffu, s0, 4);
                    s0 += __shfl_xor_sync(0xffffffffu, s0, 8);
                    s0 += __shfl_xor_sync(0xffffffffu, s0, 16);
                    s1 += __shfl_xor_sync(0xffffffffu, s1, 4);
                    s1 += __shfl_xor_sync(0xffffffffu, s1, 8);
                    s1 += __shfl_xor_sync(0xffffffffu, s1, 16);
                    if (ar == 0 && seg != SEG_SENT) {
                        atomicAdd(&out[seg * DIM + c], s0);
                        atomicAdd(&out[seg * DIM + c + 1], s1);
                    }
                }
                if (seg >= send) break;
                int c0 = (i0 > seg) ? i0 : SEG_SENT;
                int c1 = (i1 > seg) ? i1 : SEG_SENT;
                int c2 = (i2 > seg) ? i2 : SEG_SENT;
                int c3 = (i3 > seg) ? i3 : SEG_SENT;
                int nx = min(min(c0, c1), min(c2, c3));
                #pragma unroll
                for (int off = 16; off; off >>= 1)
                    nx = min(nx, __shfl_xor_sync(0xffffffffu, nx, off));
                seg = nx;
            }
        }
        // no end barrier needed: next load's sx writes are ordered by B1-B3
    }
}

// ---------------- final: out[s] = (out[s]/segsum[s]) @ W2 + b2 (0 if empty) ----------------
// bytes: sW2@0(34816) sv@34816(69632) srinv@104448(1024) b2@105472(512)
#define Z_SMEM_BYTES 105984

__global__ __launch_bounds__(NTZ, 1)
void final_kernel(const float* __restrict__ Wn2, const float* __restrict__ bn2,
                  float* __restrict__ out, int S) {
    extern __shared__ char smb[];
    __half* sW2  = (__half*)smb;
    __half* sv   = (__half*)(smb + 34816);
    float* srinv = (float*)(smb + 104448);  // 256
    float* sb2   = (float*)(smb + 105472);
    const uint32_t sW2_a = (uint32_t)__cvta_generic_to_shared(sW2);
    const uint32_t sv_a  = (uint32_t)__cvta_generic_to_shared(sv);

    const int tid = threadIdx.x;
    const int w = tid >> 5, lane = tid & 31;
    const int ar = lane >> 2, ac = lane & 3;
    const int m0 = (w & 7) * 32, n0 = (w >> 3) * 64;
    const int base = blockIdx.x * 256;

    load_w16<NTZ>(sW2, Wn2, tid);
    if (tid < DIM) sb2[tid] = bn2[tid];
    if (tid < 256) {
        int s = base + tid;
        float sum = (s < S) ? g_segsum[s] : 0.0f;
        srinv[tid] = (sum > 0.0f) ? __frcp_rn(sum) : 0.0f;
    }
    __syncthreads();

    // load V = U * rinv as half tile
    #pragma unroll
    for (int b = 0; b < 2; ++b) {
        float4 v[8]; float sc[8];
        #pragma unroll
        for (int i = 0; i < 8; ++i) {
            int q = tid + (b * 8 + i) * NTZ;
            int row = q >> 5;
            int s = base + row;
            v[i] = (s < S) ? ((const float4*)out)[(size_t)s * 32 + (q & 31)]
                           : make_float4(0.f, 0.f, 0.f, 0.f);
            sc[i] = srinv[row];
        }
        #pragma unroll
        for (int i = 0; i < 8; ++i) {
            int q = tid + (b * 8 + i) * NTZ;
            int row = q >> 5, kv = q & 31;
            uint2 pk;
            pk.x = pack_half2(v[i].x * sc[i], v[i].y * sc[i]);
            pk.y = pack_half2(v[i].z * sc[i], v[i].w * sc[i]);
            *(uint2*)&sv[row * SH + kv * 4] = pk;
        }
    }
    __syncthreads();

    float acc[2][8][4];
    zero_acc(acc);
    warp_gemm16(sv_a, sW2_a, acc, m0, n0, lane);

    #pragma unroll
    for (int mi = 0; mi < 2; ++mi) {
        int rl0 = m0 + mi * 16 + ar, rl1 = rl0 + 8;
        int r0 = base + rl0, r1 = base + rl1;
        bool nz0 = srinv[rl0] > 0.0f, nz1 = srinv[rl1] > 0.0f;
        #pragma unroll
        for (int j = 0; j < 8; ++j) {
            int c = n0 + 8 * j + 2 * ac;
            if (r0 < S) {
                out[r0 * DIM + c]     = nz0 ? acc[mi][j][0] + sb2[c]     : 0.0f;
                out[r0 * DIM + c + 1] = nz0 ? acc[mi][j][1] + sb2[c + 1] : 0.0f;
            }
            if (r1 < S) {
                out[r1 * DIM + c]     = nz1 ? acc[mi][j][2] + sb2[c]     : 0.0f;
                out[r1 * DIM + c + 1] = nz1 ? acc[mi][j][3] + sb2[c + 1] : 0.0f;
            }
        }
    }
}

// ---------------- launch ----------------
extern "C" void kernel_launch(void* const* d_in, const int* in_sizes, int n_in,
                              void* d_out, int out_size) {
    const float* x   = (const float*)d_in[0];
    const void*  idx = d_in[1];
    const float* Wg1 = (const float*)d_in[3];
    const float* bg1 = (const float*)d_in[4];
    const float* Wg2 = (const float*)d_in[5];
    const float* bg2 = (const float*)d_in[6];
    const float* Wn1 = (const float*)d_in[7];
    const float* bn1 = (const float*)d_in[8];
    const float* Wn2 = (const float*)d_in[9];
    const float* bn2 = (const float*)d_in[10];
    float* out = (float*)d_out;

    const int N = in_sizes[0] / DIM;
    const int S = out_size / DIM;

    cudaFuncSetAttribute(fused_kernel, cudaFuncAttributeMaxDynamicSharedMemorySize, F_SMEM_BYTES);
    cudaFuncSetAttribute(final_kernel, cudaFuncAttributeMaxDynamicSharedMemorySize, Z_SMEM_BYTES);

    di_kernel<<<256, 256>>>((const int*)idx, N, out, out_size, S);

    fused_kernel<<<GRID_F, NTF, F_SMEM_BYTES>>>(x, idx, Wg1, bg1, Wg2, bg2,
                                                Wn1, bn1, out, N);

    final_kernel<<<(S + 255) / 256, NTZ, Z_SMEM_BYTES>>>(Wn2, bn2, out, S);
}

// round 17
// speedup vs baseline: 1.7026x; 1.0150x over previous
#include <cuda_runtime.h>
#include <cuda_fp16.h>
#include <stdint.h>

#define DIM 128
#define TILE 128
#define NTF 256        // fused kernel threads
#define NTZ 512        // final kernel threads
#define SH 136         // half stride: word-stride 68 = 4 mod 32 -> conflict-free LDS/LDSM
#define SEG_SENT 0x7FFFFFFF
#define MAXSEG 8192
#define GRID_F 304

// ---------------- scratch ----------------
__device__ float g_segsum[MAXSEG];
__device__ int   g_idx_is64;

// ---------------- helpers ----------------
__device__ __forceinline__ float silu_f(float a) {
    return __fdividef(a, 1.0f + __expf(-a));
}
__device__ __forceinline__ uint32_t pack_half2(float lo, float hi) {
    uint32_t u; asm("cvt.rn.f16x2.f32 %0, %1, %2;" : "=r"(u) : "f"(hi), "f"(lo)); return u;
}
__device__ __forceinline__ int load_index(const void* p, int i, bool is64) {
    return is64 ? (int)((const long long*)p)[i] : ((const int*)p)[i];
}
__device__ __forceinline__ void mma_f16(float c[4], const uint32_t a[4], uint32_t b0, uint32_t b1) {
    asm volatile(
        "mma.sync.aligned.m16n8k16.row.col.f32.f16.f16.f32 "
        "{%0,%1,%2,%3}, {%4,%5,%6,%7}, {%8,%9}, {%0,%1,%2,%3};"
        : "+f"(c[0]), "+f"(c[1]), "+f"(c[2]), "+f"(c[3])
        : "r"(a[0]), "r"(a[1]), "r"(a[2]), "r"(a[3]), "r"(b0), "r"(b1));
}
__device__ __forceinline__ void ldsm_x4(uint32_t r[4], uint32_t addr) {
    asm volatile("ldmatrix.sync.aligned.m8n8.x4.shared.b16 {%0,%1,%2,%3}, [%4];"
        : "=r"(r[0]), "=r"(r[1]), "=r"(r[2]), "=r"(r[3]) : "r"(addr));
}

// W[k][n] fp32 row-major -> smem transposed half [n*SH + k], MLP-batched
template<int NT>
__device__ __forceinline__ void load_w16(__half* swh, const float* __restrict__ W, int tid) {
    #pragma unroll
    for (int b = 0; b < (DIM * DIM / 4) / (8 * NT); ++b) {
        float4 v[8];
        #pragma unroll
        for (int i = 0; i < 8; ++i) v[i] = ((const float4*)W)[tid + (b * 8 + i) * NT];
        #pragma unroll
        for (int i = 0; i < 8; ++i) {
            int q = tid + (b * 8 + i) * NT;
            int k = q >> 5, nv = (q & 31) * 4;
            swh[(nv + 0) * SH + k] = __float2half_rn(v[i].x);
            swh[(nv + 1) * SH + k] = __float2half_rn(v[i].y);
            swh[(nv + 2) * SH + k] = __float2half_rn(v[i].z);
            swh[(nv + 3) * SH + k] = __float2half_rn(v[i].w);
        }
    }
}

// fp32 128-row tile -> half smem (256 thr, 8 LDG.128 in flight)
__device__ __forceinline__ void load_x16(__half* sx, const float* __restrict__ x,
                                         int base, int N, int tid) {
    #pragma unroll
    for (int b = 0; b < 2; ++b) {
        float4 v[8];
        #pragma unroll
        for (int i = 0; i < 8; ++i) {
            int q = tid + (b * 8 + i) * NTF;
            int node = base + (q >> 5);
            v[i] = (node < N) ? ((const float4*)x)[(size_t)node * 32 + (q & 31)]
                              : make_float4(0.f, 0.f, 0.f, 0.f);
        }
        #pragma unroll
        for (int i = 0; i < 8; ++i) {
            int q = tid + (b * 8 + i) * NTF;
            int n = q >> 5, kv = q & 31;
            uint2 pk;
            pk.x = pack_half2(v[i].x, v[i].y);
            pk.y = pack_half2(v[i].z, v[i].w);
            *(uint2*)&sx[n * SH + kv * 4] = pk;
        }
    }
}

// 32x64 warp-tile GEMM with ldmatrix.x4. K=128 in 8 k16 steps.
// acc[mi][j][c]: rows m0+mi*16+{ar,ar+8}, cols n0+8j+{2ac,2ac+1}
__device__ __forceinline__ void warp_gemm16(uint32_t sx_a, uint32_t sW_a,
                                            float acc[2][8][4], int m0, int n0, int lane) {
    const uint32_t aAddr0 = sx_a + (uint32_t)((m0 + (lane & 15)) * SH + ((lane >> 4) << 3)) * 2;
    const uint32_t aAddr1 = aAddr0 + 16 * SH * 2;
    const uint32_t bAddr  = sW_a + (uint32_t)((n0 + ((lane >> 4) << 3) + (lane & 7)) * SH
                                              + (((lane >> 3) & 1) << 3)) * 2;
    #pragma unroll
    for (int ks = 0; ks < 8; ++ks) {
        const uint32_t kb = ks * 32;
        uint32_t a[2][4];
        ldsm_x4(a[0], aAddr0 + kb);
        ldsm_x4(a[1], aAddr1 + kb);
        #pragma unroll
        for (int p = 0; p < 4; ++p) {
            uint32_t b[4];
            ldsm_x4(b, bAddr + (uint32_t)(p * 16 * SH) * 2 + kb);
            mma_f16(acc[0][2 * p],     a[0], b[0], b[1]);
            mma_f16(acc[1][2 * p],     a[1], b[0], b[1]);
            mma_f16(acc[0][2 * p + 1], a[0], b[2], b[3]);
            mma_f16(acc[1][2 * p + 1], a[1], b[2], b[3]);
        }
    }
}

__device__ __forceinline__ void zero_acc(float acc[2][8][4]) {
    #pragma unroll
    for (int mi = 0; mi < 2; ++mi)
        #pragma unroll
        for (int j = 0; j < 8; ++j)
            #pragma unroll
            for (int c = 0; c < 4; ++c) acc[mi][j][c] = 0.0f;
}

// ---------------- detect + init (segsum + out zero) ----------------
__global__ void di_kernel(const int* v, int n, float* out, int out_n, int S) {
    if (blockIdx.x == 0) {
        int p = n - 1 - (int)threadIdx.x;
        int nz = 0;
        if (p >= 0 && (p & 1) && v[p] != 0) nz = 1;
        int any = __syncthreads_or(nz);
        if (threadIdx.x == 0) g_idx_is64 = any ? 0 : 1;
    }
    int i = blockIdx.x * blockDim.x + threadIdx.x;
    int stride = gridDim.x * blockDim.x;
    for (int p = i; p < out_n; p += stride) out[p] = 0.0f;
    for (int p = i; p < S; p += stride) g_segsum[p] = 0.0f;
}

// ---------------- fused: gate + exp/segsum + GEMM1 + e-weighted t scatter (U accum) ----------------
// bytes: sWg@0(34816) sW1@34816(34816) sx@69632(34816)
//        b1g@104448(512) w2g@104960(512) b1n@105472(512) sg@105984(1024)
#define F_SMEM_BYTES 107008

__global__ __launch_bounds__(NTF, 2)
void fused_kernel(const float* __restrict__ x, const void* __restrict__ idxp,
                  const float* __restrict__ Wg1, const float* __restrict__ bg1,
                  const float* __restrict__ Wg2, const float* __restrict__ bg2,
                  const float* __restrict__ Wn1, const float* __restrict__ bn1,
                  float* __restrict__ out, int N) {
    extern __shared__ char smb[];
    __half* sWg  = (__half*)smb;
    __half* sW1  = (__half*)(smb + 34816);
    __half* sx   = (__half*)(smb + 69632);
    float* sb1g  = (float*)(smb + 104448);
    float* sw2g  = (float*)(smb + 104960);
    float* sb1n  = (float*)(smb + 105472);
    float* sg    = (float*)(smb + 105984);   // [2][128] gate partials
    const uint32_t sWg_a = (uint32_t)__cvta_generic_to_shared(sWg);
    const uint32_t sW1_a = (uint32_t)__cvta_generic_to_shared(sW1);
    const uint32_t sx_a  = (uint32_t)__cvta_generic_to_shared(sx);

    const int tid = threadIdx.x;
    const int w = tid >> 5, lane = tid & 31;
    const int ar = lane >> 2, ac = lane & 3;
    const int mq = w & 3, nh = w >> 2;
    const int m0 = mq * 32, n0 = nh * 64;
    const bool is64 = (g_idx_is64 != 0);

    load_w16<NTF>(sWg, Wg1, tid);
    load_w16<NTF>(sW1, Wn1, tid);
    if (tid < DIM) {
        sb1g[tid] = bg1[tid]; sw2g[tid] = Wg2[tid]; sb1n[tid] = bn1[tid];
    }
    const float bg2v = bg2[0];
    __syncthreads();

    const int ntiles = (N + TILE - 1) / TILE;
    for (int tile = blockIdx.x; tile < ntiles; tile += GRID_F) {
        const int base = tile * TILE;

        // load x tile (sx write safety: all warps passed B2 of the previous
        // tile before any warp reaches here; all sx reads are pre-B2)
        load_x16(sx, x, base, N, tid);

        // L2 prefetch of next tile's x rows (no registers held)
        {
            int ntile = tile + GRID_F;
            if (ntile < ntiles) {
                int r0 = ntile * TILE + (tid >> 1);
                if (r0 < N) {
                    const char* pb = (const char*)(x) + (size_t)r0 * 512 + (tid & 1) * 256;
                    asm volatile("prefetch.global.L2 [%0];" :: "l"(pb));
                    asm volatile("prefetch.global.L2 [%0];" :: "l"(pb + 128));
                }
            }
        }
        __syncthreads();                 // B1: tile ready

        float acc[2][8][4];

        // ---- gate GEMM: x @ Wg1 ----
        zero_acc(acc);
        warp_gemm16(sx_a, sWg_a, acc, m0, n0, lane);

        // partial silu-dot over this warp's 64 cols, per row -> sg
        #pragma unroll
        for (int mi = 0; mi < 2; ++mi) {
            float p0 = 0.0f, p1 = 0.0f;
            #pragma unroll
            for (int j = 0; j < 8; ++j) {
                int c = n0 + 8 * j + 2 * ac;
                float s0 = sw2g[c], s1 = sw2g[c + 1];
                float u0 = sb1g[c], u1 = sb1g[c + 1];
                p0 = fmaf(silu_f(acc[mi][j][0] + u0), s0, p0);
                p0 = fmaf(silu_f(acc[mi][j][1] + u1), s1, p0);
                p1 = fmaf(silu_f(acc[mi][j][2] + u0), s0, p1);
                p1 = fmaf(silu_f(acc[mi][j][3] + u1), s1, p1);
            }
            p0 += __shfl_xor_sync(0xffffffffu, p0, 1);
            p0 += __shfl_xor_sync(0xffffffffu, p0, 2);
            p1 += __shfl_xor_sync(0xffffffffu, p1, 1);
            p1 += __shfl_xor_sync(0xffffffffu, p1, 2);
            if (ac == 0) {
                int r = m0 + mi * 16 + ar;
                sg[nh * 128 + r] = p0;
                sg[nh * 128 + r + 8] = p1;
            }
        }

        // ---- GEMM1: x @ Wn1 (independent of gate epilogue; fills issue slots) ----
        zero_acc(acc);
        warp_gemm16(sx_a, sW1_a, acc, m0, n0, lane);
        __syncthreads();                 // B2: sg visible; all sx reads done

        // per-lane e/idx for row m0+lane (redundant across nh halves; no smem)
        float e; int id;
        {
            int r = m0 + lane;
            int node = base + r;
            id = (node < N) ? load_index(idxp, node, is64) : SEG_SENT;
            float g = sg[r] + sg[128 + r] + bg2v;
            e = (id == SEG_SENT) ? 0.0f : __expf(g);
        }

        // segsum atomics: nh==0 warps only (one contribution per row)
        if (nh == 0) {
            float v = e; int vid = id;
            #pragma unroll
            for (int off = 1; off < 32; off <<= 1) {
                float ov = __shfl_down_sync(0xffffffffu, v, off);
                int  oid = __shfl_down_sync(0xffffffffu, vid, off);
                if (lane + off < 32 && oid == vid) v += ov;
            }
            int pid = __shfl_up_sync(0xffffffffu, id, 1);
            if (((lane == 0) || (pid != id)) && id != SEG_SENT) atomicAdd(&g_segsum[id], v);
        }

        // t = silu(acc + b1n) in place (fp32, never leaves registers)
        #pragma unroll
        for (int mi = 0; mi < 2; ++mi)
            #pragma unroll
            for (int j = 0; j < 8; ++j) {
                int c = n0 + 8 * j + 2 * ac;
                float u0 = sb1n[c], u1 = sb1n[c + 1];
                acc[mi][j][0] = silu_f(acc[mi][j][0] + u0);
                acc[mi][j][1] = silu_f(acc[mi][j][1] + u1);
                acc[mi][j][2] = silu_f(acc[mi][j][2] + u0);
                acc[mi][j][3] = silu_f(acc[mi][j][3] + u1);
            }

        // e-weighted segmented row-sum of t -> atomicAdd into out (U accumulation)
        // e/idx for rows m0+{ar, ar+8, ar+16, ar+24} fetched via shfl
        {
            const float a0 = __shfl_sync(0xffffffffu, e, ar);
            const float a1 = __shfl_sync(0xffffffffu, e, ar + 8);
            const float a2 = __shfl_sync(0xffffffffu, e, ar + 16);
            const float a3 = __shfl_sync(0xffffffffu, e, ar + 24);
            const int   i0 = __shfl_sync(0xffffffffu, id, ar);
            const int   i1 = __shfl_sync(0xffffffffu, id, ar + 8);
            const int   i2 = __shfl_sync(0xffffffffu, id, ar + 16);
            const int   i3 = __shfl_sync(0xffffffffu, id, ar + 24);
            int seg = __shfl_sync(0xffffffffu, id, 0);
            const int send = __shfl_sync(0xffffffffu, id, 31);
            while (true) {
                float w0 = (i0 == seg) ? a0 : 0.0f;
                float w1 = (i1 == seg) ? a1 : 0.0f;
                float w2 = (i2 == seg) ? a2 : 0.0f;
                float w3 = (i3 == seg) ? a3 : 0.0f;
                #pragma unroll
                for (int j = 0; j < 8; ++j) {
                    int c = n0 + 8 * j + 2 * ac;
                    float s0 = w0 * acc[0][j][0] + w1 * acc[0][j][2]
                             + w2 * acc[1][j][0] + w3 * acc[1][j][2];
                    float s1 = w0 * acc[0][j][1] + w1 * acc[0][j][3]
                             + w2 * acc[1][j][1] + w3 * acc[1][j][3];
                    s0 += __shfl_xor_sync(0xffffffffu, s0, 4);
                    s0 += __shfl_xor_sync(0xffffffffu, s0, 8);
                    s0 += __shfl_xor_sync(0xffffffffu, s0, 16);
                    s1 += __shfl_xor_sync(0xffffffffu, s1, 4);
                    s1 += __shfl_xor_sync(0xffffffffu, s1, 8);
                    s1 += __shfl_xor_sync(0xffffffffu, s1, 16);
                    if (ar == 0 && seg != SEG_SENT) {
                        atomicAdd(&out[seg * DIM + c], s0);
                        atomicAdd(&out[seg * DIM + c + 1], s1);
                    }
                }
                if (seg >= send) break;
                int c0 = (i0 > seg) ? i0 : SEG_SENT;
                int c1 = (i1 > seg) ? i1 : SEG_SENT;
                int c2 = (i2 > seg) ? i2 : SEG_SENT;
                int c3 = (i3 > seg) ? i3 : SEG_SENT;
                int nx = min(min(c0, c1), min(c2, c3));
                #pragma unroll
                for (int off = 16; off; off >>= 1)
                    nx = min(nx, __shfl_xor_sync(0xffffffffu, nx, off));
                seg = nx;
            }
        }
        // no end barrier: next iteration's sx writes are safe (all sx reads pre-B2)
    }
}

// ---------------- final: out[s] = (out[s]/segsum[s]) @ W2 + b2 (0 if empty) ----------------
// bytes: sW2@0(34816) sv@34816(69632) srinv@104448(1024) b2@105472(512)
#define Z_SMEM_BYTES 105984

__global__ __launch_bounds__(NTZ, 1)
void final_kernel(const float* __restrict__ Wn2, const float* __restrict__ bn2,
                  float* __restrict__ out, int S) {
    extern __shared__ char smb[];
    __half* sW2  = (__half*)smb;
    __half* sv   = (__half*)(smb + 34816);
    float* srinv = (float*)(smb + 104448);  // 256
    float* sb2   = (float*)(smb + 105472);
    const uint32_t sW2_a = (uint32_t)__cvta_generic_to_shared(sW2);
    const uint32_t sv_a  = (uint32_t)__cvta_generic_to_shared(sv);

    const int tid = threadIdx.x;
    const int w = tid >> 5, lane = tid & 31;
    const int ar = lane >> 2, ac = lane & 3;
    const int m0 = (w & 7) * 32, n0 = (w >> 3) * 64;
    const int base = blockIdx.x * 256;

    load_w16<NTZ>(sW2, Wn2, tid);
    if (tid < DIM) sb2[tid] = bn2[tid];
    if (tid < 256) {
        int s = base + tid;
        float sum = (s < S) ? g_segsum[s] : 0.0f;
        srinv[tid] = (sum > 0.0f) ? __frcp_rn(sum) : 0.0f;
    }
    __syncthreads();

    // load V = U * rinv as half tile
    #pragma unroll
    for (int b = 0; b < 2; ++b) {
        float4 v[8]; float sc[8];
        #pragma unroll
        for (int i = 0; i < 8; ++i) {
            int q = tid + (b * 8 + i) * NTZ;
            int row = q >> 5;
            int s = base + row;
            v[i] = (s < S) ? ((const float4*)out)[(size_t)s * 32 + (q & 31)]
                           : make_float4(0.f, 0.f, 0.f, 0.f);
            sc[i] = srinv[row];
        }
        #pragma unroll
        for (int i = 0; i < 8; ++i) {
            int q = tid + (b * 8 + i) * NTZ;
            int row = q >> 5, kv = q & 31;
            uint2 pk;
            pk.x = pack_half2(v[i].x * sc[i], v[i].y * sc[i]);
            pk.y = pack_half2(v[i].z * sc[i], v[i].w * sc[i]);
            *(uint2*)&sv[row * SH + kv * 4] = pk;
        }
    }
    __syncthreads();

    float acc[2][8][4];
    zero_acc(acc);
    warp_gemm16(sv_a, sW2_a, acc, m0, n0, lane);

    #pragma unroll
    for (int mi = 0; mi < 2; ++mi) {
        int rl0 = m0 + mi * 16 + ar, rl1 = rl0 + 8;
        int r0 = base + rl0, r1 = base + rl1;
        bool nz0 = srinv[rl0] > 0.0f, nz1 = srinv[rl1] > 0.0f;
        #pragma unroll
        for (int j = 0; j < 8; ++j) {
            int c = n0 + 8 * j + 2 * ac;
            if (r0 < S) {
                out[r0 * DIM + c]     = nz0 ? acc[mi][j][0] + sb2[c]     : 0.0f;
                out[r0 * DIM + c + 1] = nz0 ? acc[mi][j][1] + sb2[c + 1] : 0.0f;
            }
            if (r1 < S) {
                out[r1 * DIM + c]     = nz1 ? acc[mi][j][2] + sb2[c]     : 0.0f;
                out[r1 * DIM + c + 1] = nz1 ? acc[mi][j][3] + sb2[c + 1] : 0.0f;
            }
        }
    }
}

// ---------------- launch ----------------
extern "C" void kernel_launch(void* const* d_in, const int* in_sizes, int n_in,
                              void* d_out, int out_size) {
    const float* x   = (const float*)d_in[0];
    const void*  idx = d_in[1];
    const float* Wg1 = (const float*)d_in[3];
    const float* bg1 = (const float*)d_in[4];
    const float* Wg2 = (const float*)d_in[5];
    const float* bg2 = (const float*)d_in[6];
    const float* Wn1 = (const float*)d_in[7];
    const float* bn1 = (const float*)d_in[8];
    const float* Wn2 = (const float*)d_in[9];
    const float* bn2 = (const float*)d_in[10];
    float* out = (float*)d_out;

    const int N = in_sizes[0] / DIM;
    const int S = out_size / DIM;

    cudaFuncSetAttribute(fused_kernel, cudaFuncAttributeMaxDynamicSharedMemorySize, F_SMEM_BYTES);
    cudaFuncSetAttribute(final_kernel, cudaFuncAttributeMaxDynamicSharedMemorySize, Z_SMEM_BYTES);

    di_kernel<<<256, 256>>>((const int*)idx, N, out, out_size, S);

    fused_kernel<<<GRID_F, NTF, F_SMEM_BYTES>>>(x, idx, Wg1, bg1, Wg2, bg2,
                                                Wn1, bn1, out, N);

    final_kernel<<<(S + 255) / 256, NTZ, Z_SMEM_BYTES>>>(Wn2, bn2, out, S);
}